// round 2
// baseline (speedup 1.0000x reference)
#include <cuda_runtime.h>
#include <math.h>

#define TSEQ 100
#define BATCH 64
#define HGRU  128
#define G3    384   // 3*H

// ---------------- scratch (static __device__, no allocation) ----------------
__device__ float g_e[6400 * 128];     // embedded input (B*T, 128)
__device__ float g_gi[6400 * 768];    // gi for both directions, row stride 768
__device__ float g_y[6400 * 256];     // layer output (B,T,2H)
__device__ float g_fcin[64 * 1024];   // [enc_h(512) | dec_h(512)] per batch row

// ---------------- embedding gather ----------------
__global__ void embed_kernel(const int* __restrict__ x,
                             const float* __restrict__ emb,
                             float* __restrict__ e) {
    int row = blockIdx.x;                 // b*T + t
    int v = x[row];
    if (v > 9999) v = 9999;
    if (v < 0)    v = 0;
    e[row * 128 + threadIdx.x] = emb[v * 128 + threadIdx.x];
}

// ---------------- generic fp32 GEMM:  C[M,N] = A[M,K](lda) * W[N,K]^T + bias[N] ----------------
// 128x128 tile, 8x8 per thread, K-chunk 8, register prefetch of next chunk.
__global__ void gemm_tn(const float* __restrict__ A, int lda,
                        const float* __restrict__ W,
                        const float* __restrict__ bias,
                        float* __restrict__ C,
                        int M, int N, int K) {
    __shared__ float As[8][128];
    __shared__ float Ws[8][128];

    int t  = threadIdx.x;        // 0..255
    int tx = t & 15;
    int ty = t >> 4;
    int m0 = blockIdx.y * 128;
    int n0 = blockIdx.x * 128;

    int lr = t >> 1;             // 0..127 row within tile
    int lk = (t & 1) * 4;        // 0 or 4

    float acc[8][8];
#pragma unroll
    for (int i = 0; i < 8; i++)
#pragma unroll
        for (int j = 0; j < 8; j++) acc[i][j] = 0.f;

    // prefetch chunk 0
    float4 aR = make_float4(0.f, 0.f, 0.f, 0.f);
    float4 wR = make_float4(0.f, 0.f, 0.f, 0.f);
    if (m0 + lr < M) aR = *(const float4*)&A[(size_t)(m0 + lr) * lda + 0 + lk];
    if (n0 + lr < N) wR = *(const float4*)&W[(size_t)(n0 + lr) * K + 0 + lk];

    for (int k0 = 0; k0 < K; k0 += 8) {
        // commit current chunk to smem
        As[lk + 0][lr] = aR.x; As[lk + 1][lr] = aR.y; As[lk + 2][lr] = aR.z; As[lk + 3][lr] = aR.w;
        Ws[lk + 0][lr] = wR.x; Ws[lk + 1][lr] = wR.y; Ws[lk + 2][lr] = wR.z; Ws[lk + 3][lr] = wR.w;
        __syncthreads();

        // issue loads for next chunk (latency hidden by compute below)
        if (k0 + 8 < K) {
            aR = make_float4(0.f, 0.f, 0.f, 0.f);
            wR = make_float4(0.f, 0.f, 0.f, 0.f);
            if (m0 + lr < M) aR = *(const float4*)&A[(size_t)(m0 + lr) * lda + (k0 + 8) + lk];
            if (n0 + lr < N) wR = *(const float4*)&W[(size_t)(n0 + lr) * K + (k0 + 8) + lk];
        }

#pragma unroll
        for (int kk = 0; kk < 8; kk++) {
            float4 a0 = *(const float4*)&As[kk][ty * 4];
            float4 a1 = *(const float4*)&As[kk][64 + ty * 4];
            float4 b0 = *(const float4*)&Ws[kk][tx * 4];
            float4 b1 = *(const float4*)&Ws[kk][64 + tx * 4];
            float av[8] = {a0.x, a0.y, a0.z, a0.w, a1.x, a1.y, a1.z, a1.w};
            float bv[8] = {b0.x, b0.y, b0.z, b0.w, b1.x, b1.y, b1.z, b1.w};
#pragma unroll
            for (int i = 0; i < 8; i++)
#pragma unroll
                for (int j = 0; j < 8; j++) acc[i][j] += av[i] * bv[j];
        }
        __syncthreads();
    }

    // store with bias
#pragma unroll
    for (int i = 0; i < 8; i++) {
        int m = m0 + ((i < 4) ? (ty * 4 + i) : (64 + ty * 4 + i - 4));
        if (m >= M) continue;
#pragma unroll
        for (int j = 0; j < 8; j++) {
            int n = n0 + ((j < 4) ? (tx * 4 + j) : (64 + tx * 4 + j - 4));
            if (n >= N) continue;
            C[(size_t)m * N + n] = acc[i][j] + bias[n];
        }
    }
}

// ---------------- GRU recurrence: one CTA per (batch row, direction) ----------------
// gi row index = b*rb + tt*rt (rb=100,rt=1 normally; rb=1,rt=0 for constant decoder input)
// gi row stride is 768 (both directions packed); this CTA reads cols [dir*384, dir*384+384)
__global__ void gru_kernel(const float* __restrict__ gi_base, int rb, int rt,
                           const float* __restrict__ Whh,   // (2, 384, 128)
                           const float* __restrict__ bhh,   // (2, 384)
                           float* __restrict__ y,           // (B, T, 256)
                           float* __restrict__ hfin) {      // g_fcin + layer_off
    extern __shared__ float smem[];
    float*       sw  = smem;                  // 32*384 float4 = 49152 floats (192 KB)
    float*       sh  = smem + 49152;          // 128
    float*       sgh = sh + 128;              // 384
    float*       sgi = sgh + 384;             // 384

    int j   = threadIdx.x;    // 0..383 (gate-column)
    int b   = blockIdx.x;     // batch row
    int dir = blockIdx.y;     // 0 fwd, 1 bwd

    const float* W  = Whh + dir * G3 * HGRU;
    const float* gi = gi_base + dir * G3;
    float bh = bhh[dir * G3 + j];

    // stage Whh into smem, layout sw4[kk*384 + col] = W[col][4kk..4kk+3]
    float4* sw4 = (float4*)sw;
    const float4* Wrow = (const float4*)(W + j * HGRU);
#pragma unroll
    for (int kk = 0; kk < 32; kk++) sw4[kk * G3 + j] = Wrow[kk];
    if (j < HGRU) sh[j] = 0.f;
    __syncthreads();

    const float4* sh4 = (const float4*)sh;

    for (int t = 0; t < TSEQ; t++) {
        int tt  = dir ? (TSEQ - 1 - t) : t;
        int row = b * rb + tt * rt;
        float gval = gi[row * 768 + j];   // LDG overlaps with FMA loop below

        float acc0 = 0.f, acc1 = 0.f;
#pragma unroll
        for (int kk = 0; kk < 32; kk++) {
            float4 w4 = sw4[kk * G3 + j];
            float4 h4 = sh4[kk];          // broadcast across CTA
            acc0 += w4.x * h4.x; acc1 += w4.y * h4.y;
            acc0 += w4.z * h4.z; acc1 += w4.w * h4.w;
        }
        sgh[j] = acc0 + acc1 + bh;
        sgi[j] = gval;
        __syncthreads();

        if (j < HGRU) {
            float r = 1.f / (1.f + expf(-(sgi[j]          + sgh[j])));
            float z = 1.f / (1.f + expf(-(sgi[HGRU + j]   + sgh[HGRU + j])));
            float n = tanhf(sgi[2 * HGRU + j] + r * sgh[2 * HGRU + j]);
            float hn = n + z * (sh[j] - n);
            sh[j] = hn;
            y[(b * TSEQ + tt) * 256 + dir * HGRU + j] = hn;
        }
        __syncthreads();
    }
    if (j < HGRU) hfin[b * 1024 + dir * HGRU + j] = sh[j];
}

// ---------------- driver ----------------
extern "C" void kernel_launch(void* const* d_in, const int* in_sizes, int n_in,
                              void* d_out, int out_size) {
    const int* x         = (const int*)d_in[0];
    const float* emb     = (const float*)d_in[1];
    const float* eWih0   = (const float*)d_in[2];
    const float* eWhh0   = (const float*)d_in[3];
    const float* ebih0   = (const float*)d_in[4];
    const float* ebhh0   = (const float*)d_in[5];
    const float* eWih1   = (const float*)d_in[6];
    const float* eWhh1   = (const float*)d_in[7];
    const float* ebih1   = (const float*)d_in[8];
    const float* ebhh1   = (const float*)d_in[9];
    const float* dWih0   = (const float*)d_in[10];
    const float* dWhh0   = (const float*)d_in[11];
    const float* dbih0   = (const float*)d_in[12];
    const float* dbhh0   = (const float*)d_in[13];
    const float* dWih1   = (const float*)d_in[14];
    const float* dWhh1   = (const float*)d_in[15];
    const float* dbih1   = (const float*)d_in[16];
    const float* dbhh1   = (const float*)d_in[17];
    const float* fcW     = (const float*)d_in[18];
    const float* fcb     = (const float*)d_in[19];
    const float* recW    = (const float*)d_in[20];
    const float* recb    = (const float*)d_in[21];

    float* out = (float*)d_out;          // (64, 20)
    float* rec = out + 64 * 20;          // (64, 100, 10000)

    float *e, *gi, *y, *fcin;
    cudaGetSymbolAddress((void**)&e,    g_e);
    cudaGetSymbolAddress((void**)&gi,   g_gi);
    cudaGetSymbolAddress((void**)&y,    g_y);
    cudaGetSymbolAddress((void**)&fcin, g_fcin);

    const int GRU_SMEM = (49152 + 128 + 384 + 384) * 4;  // 200192 B
    cudaFuncSetAttribute(gru_kernel, cudaFuncAttributeMaxDynamicSharedMemorySize, GRU_SMEM);

    dim3 gruGrid(BATCH, 2);

    // 1. embedding
    embed_kernel<<<6400, 128>>>(x, emb, e);

    // 2. encoder layer 0
    gemm_tn<<<dim3(6, 50), 256>>>(e, 128, eWih0, ebih0, gi, 6400, 768, 128);
    gru_kernel<<<gruGrid, 384, GRU_SMEM>>>(gi, TSEQ, 1, eWhh0, ebhh0, y, fcin + 0);

    // 3. encoder layer 1
    gemm_tn<<<dim3(6, 50), 256>>>(y, 256, eWih1, ebih1, gi, 6400, 768, 256);
    gru_kernel<<<gruGrid, 384, GRU_SMEM>>>(gi, TSEQ, 1, eWhh1, ebhh1, y, fcin + 256);

    // 4. decoder layer 0 (constant input: gi computed once per batch row)
    gemm_tn<<<dim3(6, 1), 256>>>(fcin, 1024, dWih0, dbih0, gi, 64, 768, 512);
    gru_kernel<<<gruGrid, 384, GRU_SMEM>>>(gi, 1, 0, dWhh0, dbhh0, y, fcin + 512);

    // 5. decoder layer 1 (output y = rec_seq)
    gemm_tn<<<dim3(6, 50), 256>>>(y, 256, dWih1, dbih1, gi, 6400, 768, 256);
    gru_kernel<<<gruGrid, 384, GRU_SMEM>>>(gi, TSEQ, 1, dWhh1, dbhh1, y, fcin + 768);

    // 6. classifier head: out = [enc_h, dec_h] @ fc_W^T + fc_b
    gemm_tn<<<dim3(1, 1), 256>>>(fcin, 1024, fcW, fcb, out, 64, 20, 1024);

    // 7. reconstruction: rec = rec_seq @ rec_W^T + rec_b   (the big one)
    gemm_tn<<<dim3(79, 50), 256>>>(y, 256, recW, recb, rec, 6400, 10000, 256);
}

// round 3
// speedup vs baseline: 1.8311x; 1.8311x over previous
#include <cuda_runtime.h>
#include <math.h>

#define TSEQ 100
#define BATCH 64
#define HGRU  128
#define G3    384   // 3*H

// ---------------- scratch (static __device__, no allocation) ----------------
__device__ float g_e[6400 * 128];     // embedded input (B*T, 128)
__device__ float g_gi[6400 * 768];    // gi for both directions, row stride 768
__device__ float g_y[6400 * 256];     // layer output (B,T,2H)
__device__ float g_fcin[64 * 1024];   // [enc_h(512) | dec_h(512)] per batch row

// ---------------- embedding gather ----------------
__global__ void embed_kernel(const int* __restrict__ x,
                             const float* __restrict__ emb,
                             float* __restrict__ e) {
    int row = blockIdx.x;                 // b*T + t
    int v = x[row];
    if (v > 9999) v = 9999;
    if (v < 0)    v = 0;
    e[row * 128 + threadIdx.x] = emb[v * 128 + threadIdx.x];
}

// ---------------- generic fp32 GEMM:  C[M,N] = A[M,K](lda) * W[N,K]^T + bias[N] ----------------
__global__ void gemm_tn(const float* __restrict__ A, int lda,
                        const float* __restrict__ W,
                        const float* __restrict__ bias,
                        float* __restrict__ C,
                        int M, int N, int K) {
    __shared__ float As[8][128];
    __shared__ float Ws[8][128];

    int t  = threadIdx.x;        // 0..255
    int tx = t & 15;
    int ty = t >> 4;
    int m0 = blockIdx.y * 128;
    int n0 = blockIdx.x * 128;

    int lr = t >> 1;             // 0..127 row within tile
    int lk = (t & 1) * 4;        // 0 or 4

    float acc[8][8];
#pragma unroll
    for (int i = 0; i < 8; i++)
#pragma unroll
        for (int j = 0; j < 8; j++) acc[i][j] = 0.f;

    float4 aR = make_float4(0.f, 0.f, 0.f, 0.f);
    float4 wR = make_float4(0.f, 0.f, 0.f, 0.f);
    if (m0 + lr < M) aR = *(const float4*)&A[(size_t)(m0 + lr) * lda + 0 + lk];
    if (n0 + lr < N) wR = *(const float4*)&W[(size_t)(n0 + lr) * K + 0 + lk];

    for (int k0 = 0; k0 < K; k0 += 8) {
        As[lk + 0][lr] = aR.x; As[lk + 1][lr] = aR.y; As[lk + 2][lr] = aR.z; As[lk + 3][lr] = aR.w;
        Ws[lk + 0][lr] = wR.x; Ws[lk + 1][lr] = wR.y; Ws[lk + 2][lr] = wR.z; Ws[lk + 3][lr] = wR.w;
        __syncthreads();

        if (k0 + 8 < K) {
            aR = make_float4(0.f, 0.f, 0.f, 0.f);
            wR = make_float4(0.f, 0.f, 0.f, 0.f);
            if (m0 + lr < M) aR = *(const float4*)&A[(size_t)(m0 + lr) * lda + (k0 + 8) + lk];
            if (n0 + lr < N) wR = *(const float4*)&W[(size_t)(n0 + lr) * K + (k0 + 8) + lk];
        }

#pragma unroll
        for (int kk = 0; kk < 8; kk++) {
            float4 a0 = *(const float4*)&As[kk][ty * 4];
            float4 a1 = *(const float4*)&As[kk][64 + ty * 4];
            float4 b0 = *(const float4*)&Ws[kk][tx * 4];
            float4 b1 = *(const float4*)&Ws[kk][64 + tx * 4];
            float av[8] = {a0.x, a0.y, a0.z, a0.w, a1.x, a1.y, a1.z, a1.w};
            float bv[8] = {b0.x, b0.y, b0.z, b0.w, b1.x, b1.y, b1.z, b1.w};
#pragma unroll
            for (int i = 0; i < 8; i++)
#pragma unroll
                for (int j = 0; j < 8; j++) acc[i][j] += av[i] * bv[j];
        }
        __syncthreads();
    }

#pragma unroll
    for (int i = 0; i < 8; i++) {
        int m = m0 + ((i < 4) ? (ty * 4 + i) : (64 + ty * 4 + i - 4));
        if (m >= M) continue;
#pragma unroll
        for (int j = 0; j < 8; j++) {
            int n = n0 + ((j < 4) ? (tx * 4 + j) : (64 + tx * 4 + j - 4));
            if (n >= N) continue;
            C[(size_t)m * N + n] = acc[i][j] + bias[n];
        }
    }
}

// ---------------- GRU recurrence: Whh register-resident, one CTA per (b, dir) ----------------
__global__ void __launch_bounds__(384, 1)
gru_kernel(const float* __restrict__ gi_base, int rb, int rt,
           const float* __restrict__ Whh,   // (2, 384, 128)
           const float* __restrict__ bhh,   // (2, 384)
           float* __restrict__ y,           // (B, T, 256)
           float* __restrict__ hfin) {
    __shared__ float sh[128];
    __shared__ float sgh[G3];
    __shared__ float sgi[G3];

    int j   = threadIdx.x;    // 0..383 (gate-column)
    int b   = blockIdx.x;     // batch row
    int dir = blockIdx.y;     // 0 fwd, 1 bwd

    const float* gi = gi_base + dir * G3;
    float bh = bhh[dir * G3 + j];

    // pull this column's Whh row (128 floats) into registers
    float4 w[32];
    const float4* Wrow = (const float4*)(Whh + (dir * G3 + j) * HGRU);
#pragma unroll
    for (int kk = 0; kk < 32; kk++) w[kk] = Wrow[kk];

    if (j < HGRU) sh[j] = 0.f;
    __syncthreads();

    const float4* sh4 = (const float4*)sh;

    for (int t = 0; t < TSEQ; t++) {
        int tt  = dir ? (TSEQ - 1 - t) : t;
        int row = b * rb + tt * rt;
        float gval = gi[row * 768 + j];   // LDG overlaps with FMA loop

        float acc0 = 0.f, acc1 = 0.f, acc2 = 0.f, acc3 = 0.f;
#pragma unroll
        for (int kk = 0; kk < 32; kk++) {
            float4 h4 = sh4[kk];          // broadcast
            acc0 += w[kk].x * h4.x;
            acc1 += w[kk].y * h4.y;
            acc2 += w[kk].z * h4.z;
            acc3 += w[kk].w * h4.w;
        }
        sgh[j] = (acc0 + acc1) + (acc2 + acc3) + bh;
        sgi[j] = gval;
        __syncthreads();

        if (j < HGRU) {
            float r = 1.f / (1.f + expf(-(sgi[j]          + sgh[j])));
            float z = 1.f / (1.f + expf(-(sgi[HGRU + j]   + sgh[HGRU + j])));
            float n = tanhf(sgi[2 * HGRU + j] + r * sgh[2 * HGRU + j]);
            float hn = n + z * (sh[j] - n);
            sh[j] = hn;
            y[(b * TSEQ + tt) * 256 + dir * HGRU + j] = hn;
        }
        __syncthreads();
    }
    if (j < HGRU) hfin[b * 1024 + dir * HGRU + j] = sh[j];
}

// ---------------- tf32 helpers ----------------
__device__ __forceinline__ unsigned f2tf32(float x) {
    unsigned u;
    asm("cvt.rna.tf32.f32 %0, %1;" : "=r"(u) : "f"(x));
    return u;
}

__device__ __forceinline__ void mma_tf32(float* d, const unsigned* a, const unsigned* b) {
    asm volatile(
        "mma.sync.aligned.m16n8k8.row.col.f32.tf32.tf32.f32 "
        "{%0,%1,%2,%3}, {%4,%5,%6,%7}, {%8,%9}, {%0,%1,%2,%3};"
        : "+f"(d[0]), "+f"(d[1]), "+f"(d[2]), "+f"(d[3])
        : "r"(a[0]), "r"(a[1]), "r"(a[2]), "r"(a[3]),
          "r"(b[0]), "r"(b[1]));
}

// ---------------- rec GEMM (tf32 tensor cores):  C[M,N] = A[M,256] * W[N,256]^T + bias ----------------
// 128x128 CTA tile, 8 warps (4M x 2N), warp tile 32x64, K-chunk 32.
#define RK 256
__global__ void __launch_bounds__(256)
rec_mma(const float* __restrict__ A,     // (M, 256)
        const float* __restrict__ W,     // (N, 256)
        const float* __restrict__ bias,  // (N)
        float* __restrict__ C,
        int M, int N) {
    // stride 36: bank = 4*r + c (mod 32) -> conflict-free fragment reads
    __shared__ unsigned As[128][36];
    __shared__ unsigned Bs[128][36];

    int t    = threadIdx.x;
    int lane = t & 31;
    int warp = t >> 5;
    int m0 = blockIdx.y * 128;
    int n0 = blockIdx.x * 128;
    int wm = (warp & 3) * 32;
    int wn = (warp >> 2) * 64;
    int r  = lane >> 2;       // 0..7
    int c  = lane & 3;        // 0..3

    float acc[2][8][4];
#pragma unroll
    for (int mf = 0; mf < 2; mf++)
#pragma unroll
        for (int nf = 0; nf < 8; nf++)
#pragma unroll
            for (int i = 0; i < 4; i++) acc[mf][nf][i] = 0.f;

    for (int k0 = 0; k0 < RK; k0 += 32) {
        // stage A tile (128 x 32) : 1024 float4 loads over 256 threads
#pragma unroll
        for (int i = 0; i < 4; i++) {
            int idx = i * 256 + t;
            int row = idx >> 3;
            int c4  = (idx & 7) * 4;
            float4 v = *(const float4*)&A[(size_t)(m0 + row) * RK + k0 + c4];
            unsigned* dst = &As[row][c4];
            dst[0] = f2tf32(v.x); dst[1] = f2tf32(v.y);
            dst[2] = f2tf32(v.z); dst[3] = f2tf32(v.w);
        }
        // stage W tile (128 x 32) with row guard
#pragma unroll
        for (int i = 0; i < 4; i++) {
            int idx = i * 256 + t;
            int row = idx >> 3;
            int c4  = (idx & 7) * 4;
            float4 v = make_float4(0.f, 0.f, 0.f, 0.f);
            if (n0 + row < N) v = *(const float4*)&W[(size_t)(n0 + row) * RK + k0 + c4];
            unsigned* dst = &Bs[row][c4];
            dst[0] = f2tf32(v.x); dst[1] = f2tf32(v.y);
            dst[2] = f2tf32(v.z); dst[3] = f2tf32(v.w);
        }
        __syncthreads();

#pragma unroll
        for (int ks = 0; ks < 4; ks++) {
            int kb = ks * 8;
            unsigned a[2][4];
#pragma unroll
            for (int mf = 0; mf < 2; mf++) {
                int mr = wm + mf * 16 + r;
                a[mf][0] = As[mr    ][kb + c];
                a[mf][1] = As[mr + 8][kb + c];
                a[mf][2] = As[mr    ][kb + c + 4];
                a[mf][3] = As[mr + 8][kb + c + 4];
            }
#pragma unroll
            for (int nf = 0; nf < 8; nf++) {
                unsigned b[2];
                int nr = wn + nf * 8 + r;
                b[0] = Bs[nr][kb + c];
                b[1] = Bs[nr][kb + c + 4];
                mma_tf32(acc[0][nf], a[0], b);
                mma_tf32(acc[1][nf], a[1], b);
            }
        }
        __syncthreads();
    }

    // epilogue: c0,c1 -> (row, 2c..2c+1), c2,c3 -> (row+8, 2c..2c+1)
#pragma unroll
    for (int mf = 0; mf < 2; mf++) {
#pragma unroll
        for (int nf = 0; nf < 8; nf++) {
            int n = n0 + wn + nf * 8 + 2 * c;
            if (n >= N) continue;
            float bv0 = bias[n];
            float bv1 = bias[n + 1];
            int m = m0 + wm + mf * 16 + r;
            float2 v0 = make_float2(acc[mf][nf][0] + bv0, acc[mf][nf][1] + bv1);
            float2 v1 = make_float2(acc[mf][nf][2] + bv0, acc[mf][nf][3] + bv1);
            *(float2*)&C[(size_t)m * N + n]       = v0;
            *(float2*)&C[(size_t)(m + 8) * N + n] = v1;
        }
    }
}

// ---------------- driver ----------------
extern "C" void kernel_launch(void* const* d_in, const int* in_sizes, int n_in,
                              void* d_out, int out_size) {
    const int* x         = (const int*)d_in[0];
    const float* emb     = (const float*)d_in[1];
    const float* eWih0   = (const float*)d_in[2];
    const float* eWhh0   = (const float*)d_in[3];
    const float* ebih0   = (const float*)d_in[4];
    const float* ebhh0   = (const float*)d_in[5];
    const float* eWih1   = (const float*)d_in[6];
    const float* eWhh1   = (const float*)d_in[7];
    const float* ebih1   = (const float*)d_in[8];
    const float* ebhh1   = (const float*)d_in[9];
    const float* dWih0   = (const float*)d_in[10];
    const float* dWhh0   = (const float*)d_in[11];
    const float* dbih0   = (const float*)d_in[12];
    const float* dbhh0   = (const float*)d_in[13];
    const float* dWih1   = (const float*)d_in[14];
    const float* dWhh1   = (const float*)d_in[15];
    const float* dbih1   = (const float*)d_in[16];
    const float* dbhh1   = (const float*)d_in[17];
    const float* fcW     = (const float*)d_in[18];
    const float* fcb     = (const float*)d_in[19];
    const float* recW    = (const float*)d_in[20];
    const float* recb    = (const float*)d_in[21];

    float* out = (float*)d_out;          // (64, 20)
    float* rec = out + 64 * 20;          // (64, 100, 10000)

    float *e, *gi, *y, *fcin;
    cudaGetSymbolAddress((void**)&e,    g_e);
    cudaGetSymbolAddress((void**)&gi,   g_gi);
    cudaGetSymbolAddress((void**)&y,    g_y);
    cudaGetSymbolAddress((void**)&fcin, g_fcin);

    dim3 gruGrid(BATCH, 2);

    // 1. embedding
    embed_kernel<<<6400, 128>>>(x, emb, e);

    // 2. encoder layer 0
    gemm_tn<<<dim3(6, 50), 256>>>(e, 128, eWih0, ebih0, gi, 6400, 768, 128);
    gru_kernel<<<gruGrid, 384>>>(gi, TSEQ, 1, eWhh0, ebhh0, y, fcin + 0);

    // 3. encoder layer 1
    gemm_tn<<<dim3(6, 50), 256>>>(y, 256, eWih1, ebih1, gi, 6400, 768, 256);
    gru_kernel<<<gruGrid, 384>>>(gi, TSEQ, 1, eWhh1, ebhh1, y, fcin + 256);

    // 4. decoder layer 0 (constant input over T: gi computed once per batch row)
    gemm_tn<<<dim3(6, 1), 256>>>(fcin, 1024, dWih0, dbih0, gi, 64, 768, 512);
    gru_kernel<<<gruGrid, 384>>>(gi, 1, 0, dWhh0, dbhh0, y, fcin + 512);

    // 5. decoder layer 1 (output y = rec_seq)
    gemm_tn<<<dim3(6, 50), 256>>>(y, 256, dWih1, dbih1, gi, 6400, 768, 256);
    gru_kernel<<<gruGrid, 384>>>(gi, TSEQ, 1, dWhh1, dbhh1, y, fcin + 768);

    // 6. classifier head: out = [enc_h, dec_h] @ fc_W^T + fc_b
    gemm_tn<<<dim3(1, 1), 256>>>(fcin, 1024, fcW, fcb, out, 64, 20, 1024);

    // 7. reconstruction (tf32 tensor cores): rec = rec_seq @ rec_W^T + rec_b
    rec_mma<<<dim3(79, 50), 256>>>(y, recW, recb, rec, 6400, 10000);
}

// round 6
// speedup vs baseline: 1.9618x; 1.0713x over previous
#include <cuda_runtime.h>
#include <math.h>

#define TSEQ 100
#define BATCH 64
#define HGRU  128
#define G3    384   // 3*H

// ---------------- scratch (static __device__, no allocation) ----------------
__device__ float g_e[6400 * 128];     // embedded input (B*T, 128)
__device__ float g_gi[6400 * 768];    // gi for both directions, row stride 768
__device__ float g_y[6400 * 256];     // layer output (B,T,2H)
__device__ float g_fcin[64 * 1024];   // [enc_h(512) | dec_h(512)] per batch row

// ---------------- embedding gather ----------------
__global__ void embed_kernel(const int* __restrict__ x,
                             const float* __restrict__ emb,
                             float* __restrict__ e) {
    int row = blockIdx.x;                 // b*T + t
    int v = x[row];
    if (v > 9999) v = 9999;
    if (v < 0)    v = 0;
    e[row * 128 + threadIdx.x] = emb[v * 128 + threadIdx.x];
}

// ---------------- small fp32 GEMM (classifier head only) ----------------
__global__ void gemm_tn(const float* __restrict__ A, int lda,
                        const float* __restrict__ W,
                        const float* __restrict__ bias,
                        float* __restrict__ C,
                        int M, int N, int K) {
    __shared__ float As[8][128];
    __shared__ float Ws[8][128];

    int t  = threadIdx.x;        // 0..255
    int tx = t & 15;
    int ty = t >> 4;
    int m0 = blockIdx.y * 128;
    int n0 = blockIdx.x * 128;

    int lr = t >> 1;
    int lk = (t & 1) * 4;

    float acc[8][8];
#pragma unroll
    for (int i = 0; i < 8; i++)
#pragma unroll
        for (int j = 0; j < 8; j++) acc[i][j] = 0.f;

    float4 aR = make_float4(0.f, 0.f, 0.f, 0.f);
    float4 wR = make_float4(0.f, 0.f, 0.f, 0.f);
    if (m0 + lr < M) aR = *(const float4*)&A[(size_t)(m0 + lr) * lda + 0 + lk];
    if (n0 + lr < N) wR = *(const float4*)&W[(size_t)(n0 + lr) * K + 0 + lk];

    for (int k0 = 0; k0 < K; k0 += 8) {
        As[lk + 0][lr] = aR.x; As[lk + 1][lr] = aR.y; As[lk + 2][lr] = aR.z; As[lk + 3][lr] = aR.w;
        Ws[lk + 0][lr] = wR.x; Ws[lk + 1][lr] = wR.y; Ws[lk + 2][lr] = wR.z; Ws[lk + 3][lr] = wR.w;
        __syncthreads();

        if (k0 + 8 < K) {
            aR = make_float4(0.f, 0.f, 0.f, 0.f);
            wR = make_float4(0.f, 0.f, 0.f, 0.f);
            if (m0 + lr < M) aR = *(const float4*)&A[(size_t)(m0 + lr) * lda + (k0 + 8) + lk];
            if (n0 + lr < N) wR = *(const float4*)&W[(size_t)(n0 + lr) * K + (k0 + 8) + lk];
        }

#pragma unroll
        for (int kk = 0; kk < 8; kk++) {
            float4 a0 = *(const float4*)&As[kk][ty * 4];
            float4 a1 = *(const float4*)&As[kk][64 + ty * 4];
            float4 b0 = *(const float4*)&Ws[kk][tx * 4];
            float4 b1 = *(const float4*)&Ws[kk][64 + tx * 4];
            float av[8] = {a0.x, a0.y, a0.z, a0.w, a1.x, a1.y, a1.z, a1.w};
            float bv[8] = {b0.x, b0.y, b0.z, b0.w, b1.x, b1.y, b1.z, b1.w};
#pragma unroll
            for (int i = 0; i < 8; i++)
#pragma unroll
                for (int j = 0; j < 8; j++) acc[i][j] += av[i] * bv[j];
        }
        __syncthreads();
    }

#pragma unroll
    for (int i = 0; i < 8; i++) {
        int m = m0 + ((i < 4) ? (ty * 4 + i) : (64 + ty * 4 + i - 4));
        if (m >= M) continue;
#pragma unroll
        for (int j = 0; j < 8; j++) {
            int n = n0 + ((j < 4) ? (tx * 4 + j) : (64 + tx * 4 + j - 4));
            if (n >= N) continue;
            C[(size_t)m * N + n] = acc[i][j] + bias[n];
        }
    }
}

// ---------------- GRU recurrence: Whh register-resident, one CTA per (b, dir) ----------------
__global__ void __launch_bounds__(384, 1)
gru_kernel(const float* __restrict__ gi_base, int rb, int rt,
           const float* __restrict__ Whh,   // (2, 384, 128)
           const float* __restrict__ bhh,   // (2, 384)
           float* __restrict__ y,           // (B, T, 256)
           float* __restrict__ hfin) {
    __shared__ float sh[128];
    __shared__ float sgh[G3];
    __shared__ float sgi[G3];

    int j   = threadIdx.x;    // 0..383 (gate-column)
    int b   = blockIdx.x;     // batch row
    int dir = blockIdx.y;     // 0 fwd, 1 bwd

    const float* gi = gi_base + dir * G3;
    float bh = bhh[dir * G3 + j];

    // pull this column's Whh row (128 floats) into registers
    float4 w[32];
    const float4* Wrow = (const float4*)(Whh + (dir * G3 + j) * HGRU);
#pragma unroll
    for (int kk = 0; kk < 32; kk++) w[kk] = Wrow[kk];

    if (j < HGRU) sh[j] = 0.f;
    __syncthreads();

    const float4* sh4 = (const float4*)sh;

    for (int t = 0; t < TSEQ; t++) {
        int tt  = dir ? (TSEQ - 1 - t) : t;
        int row = b * rb + tt * rt;
        float gval = gi[row * 768 + j];   // LDG overlaps with FMA loop

        float acc0 = 0.f, acc1 = 0.f, acc2 = 0.f, acc3 = 0.f;
#pragma unroll
        for (int kk = 0; kk < 32; kk++) {
            float4 h4 = sh4[kk];          // broadcast
            acc0 += w[kk].x * h4.x;
            acc1 += w[kk].y * h4.y;
            acc2 += w[kk].z * h4.z;
            acc3 += w[kk].w * h4.w;
        }
        sgh[j] = (acc0 + acc1) + (acc2 + acc3) + bh;
        sgi[j] = gval;
        __syncthreads();

        if (j < HGRU) {
            float r = __fdividef(1.f, 1.f + __expf(-(sgi[j]        + sgh[j])));
            float z = __fdividef(1.f, 1.f + __expf(-(sgi[HGRU + j] + sgh[HGRU + j])));
            float nx = sgi[2 * HGRU + j] + r * sgh[2 * HGRU + j];
            float et = __expf(-2.f * nx);
            float n  = __fdividef(1.f - et, 1.f + et);   // tanh(nx)
            float hn = n + z * (sh[j] - n);
            sh[j] = hn;
            y[(b * TSEQ + tt) * 256 + dir * HGRU + j] = hn;
        }
        __syncthreads();
    }
    if (j < HGRU) hfin[b * 1024 + dir * HGRU + j] = sh[j];
}

// ---------------- tf32 helpers ----------------
__device__ __forceinline__ unsigned f2tf32(float x) {
    unsigned u;
    asm("cvt.rna.tf32.f32 %0, %1;" : "=r"(u) : "f"(x));
    return u;
}

__device__ __forceinline__ void mma_tf32(float* d, const unsigned* a, const unsigned* b) {
    asm volatile(
        "mma.sync.aligned.m16n8k8.row.col.f32.tf32.tf32.f32 "
        "{%0,%1,%2,%3}, {%4,%5,%6,%7}, {%8,%9}, {%0,%1,%2,%3};"
        : "+f"(d[0]), "+f"(d[1]), "+f"(d[2]), "+f"(d[3])
        : "r"(a[0]), "r"(a[1]), "r"(a[2]), "r"(b[0]), "r"(b[1])
        , "r"(a[3]));
}

// NOTE: operand order must match the asm template exactly — use a clean wrapper:
__device__ __forceinline__ void mma_tf32v(float* d, const unsigned* a, const unsigned* b) {
    asm volatile(
        "mma.sync.aligned.m16n8k8.row.col.f32.tf32.tf32.f32 "
        "{%0,%1,%2,%3}, {%4,%5,%6,%7}, {%8,%9}, {%0,%1,%2,%3};"
        : "+f"(d[0]), "+f"(d[1]), "+f"(d[2]), "+f"(d[3])
        : "r"(a[0]), "r"(a[1]), "r"(a[2]), "r"(a[3]),
          "r"(b[0]), "r"(b[1]));
}

// ---------------- unified tf32 MMA GEMM:  C[M,N] = A[M,K](lda) * W[N,K]^T + bias ----------------
// 128x128 CTA tile, 8 warps (4M x 2N), warp tile 32x64, K-chunk 32,
// register-prefetch of next chunk (single smem buffer, loads in flight during compute).
__global__ void __launch_bounds__(256)
mma_tn(const float* __restrict__ A, int lda,
       const float* __restrict__ W,     // (N, K)
       const float* __restrict__ bias,  // (N)
       float* __restrict__ C,
       int M, int N, int K) {
    // stride 36: bank = 4*r + c (mod 32) -> conflict-free fragment reads
    __shared__ unsigned As[128][36];
    __shared__ unsigned Bs[128][36];

    int t    = threadIdx.x;
    int lane = t & 31;
    int warp = t >> 5;
    int m0 = blockIdx.y * 128;
    int n0 = blockIdx.x * 128;
    int wm = (warp & 3) * 32;
    int wn = (warp >> 2) * 64;
    int r  = lane >> 2;       // 0..7
    int c  = lane & 3;        // 0..3

    // staging coordinates (same for A and W): 4 iterations x 256 threads
    int srow = 0, sc4 = 0;    // computed per-iteration below

    float acc[2][8][4];
#pragma unroll
    for (int mf = 0; mf < 2; mf++)
#pragma unroll
        for (int nf = 0; nf < 8; nf++)
#pragma unroll
            for (int i = 0; i < 4; i++) acc[mf][nf][i] = 0.f;

    float4 aR[4], wR[4];

    // prefetch chunk 0
#pragma unroll
    for (int i = 0; i < 4; i++) {
        int idx = i * 256 + t;
        int row = idx >> 3;
        int c4  = (idx & 7) * 4;
        aR[i] = make_float4(0.f, 0.f, 0.f, 0.f);
        wR[i] = make_float4(0.f, 0.f, 0.f, 0.f);
        if (m0 + row < M) aR[i] = *(const float4*)&A[(size_t)(m0 + row) * lda + c4];
        if (n0 + row < N) wR[i] = *(const float4*)&W[(size_t)(n0 + row) * K + c4];
    }

    for (int k0 = 0; k0 < K; k0 += 32) {
        // commit current chunk to smem (with tf32 conversion)
#pragma unroll
        for (int i = 0; i < 4; i++) {
            int idx = i * 256 + t;
            int row = idx >> 3;
            int c4  = (idx & 7) * 4;
            unsigned* da = &As[row][c4];
            da[0] = f2tf32(aR[i].x); da[1] = f2tf32(aR[i].y);
            da[2] = f2tf32(aR[i].z); da[3] = f2tf32(aR[i].w);
            unsigned* db = &Bs[row][c4];
            db[0] = f2tf32(wR[i].x); db[1] = f2tf32(wR[i].y);
            db[2] = f2tf32(wR[i].z); db[3] = f2tf32(wR[i].w);
        }
        __syncthreads();

        // issue loads for next chunk — latency hidden behind the MMA block
        if (k0 + 32 < K) {
#pragma unroll
            for (int i = 0; i < 4; i++) {
                int idx = i * 256 + t;
                int row = idx >> 3;
                int c4  = (idx & 7) * 4;
                aR[i] = make_float4(0.f, 0.f, 0.f, 0.f);
                wR[i] = make_float4(0.f, 0.f, 0.f, 0.f);
                if (m0 + row < M) aR[i] = *(const float4*)&A[(size_t)(m0 + row) * lda + (k0 + 32) + c4];
                if (n0 + row < N) wR[i] = *(const float4*)&W[(size_t)(n0 + row) * K + (k0 + 32) + c4];
            }
        }

#pragma unroll
        for (int ks = 0; ks < 4; ks++) {
            int kb = ks * 8;
            unsigned a[2][4];
#pragma unroll
            for (int mf = 0; mf < 2; mf++) {
                int mr = wm + mf * 16 + r;
                a[mf][0] = As[mr    ][kb + c];
                a[mf][1] = As[mr + 8][kb + c];
                a[mf][2] = As[mr    ][kb + c + 4];
                a[mf][3] = As[mr + 8][kb + c + 4];
            }
#pragma unroll
            for (int nf = 0; nf < 8; nf++) {
                unsigned b[2];
                int nr = wn + nf * 8 + r;
                b[0] = Bs[nr][kb + c];
                b[1] = Bs[nr][kb + c + 4];
                mma_tf32v(acc[0][nf], a[0], b);
                mma_tf32v(acc[1][nf], a[1], b);
            }
        }
        __syncthreads();
    }

    // epilogue: c0,c1 -> (row, 2c..2c+1), c2,c3 -> (row+8, 2c..2c+1)
#pragma unroll
    for (int mf = 0; mf < 2; mf++) {
#pragma unroll
        for (int nf = 0; nf < 8; nf++) {
            int n = n0 + wn + nf * 8 + 2 * c;
            if (n >= N) continue;
            float bv0 = bias[n];
            float bv1 = bias[n + 1];
            int m = m0 + wm + mf * 16 + r;
            if (m < M) {
                *(float2*)&C[(size_t)m * N + n] =
                    make_float2(acc[mf][nf][0] + bv0, acc[mf][nf][1] + bv1);
            }
            if (m + 8 < M) {
                *(float2*)&C[(size_t)(m + 8) * N + n] =
                    make_float2(acc[mf][nf][2] + bv0, acc[mf][nf][3] + bv1);
            }
        }
    }
}

// ---------------- driver ----------------
extern "C" void kernel_launch(void* const* d_in, const int* in_sizes, int n_in,
                              void* d_out, int out_size) {
    const int* x         = (const int*)d_in[0];
    const float* emb     = (const float*)d_in[1];
    const float* eWih0   = (const float*)d_in[2];
    const float* eWhh0   = (const float*)d_in[3];
    const float* ebih0   = (const float*)d_in[4];
    const float* ebhh0   = (const float*)d_in[5];
    const float* eWih1   = (const float*)d_in[6];
    const float* eWhh1   = (const float*)d_in[7];
    const float* ebih1   = (const float*)d_in[8];
    const float* ebhh1   = (const float*)d_in[9];
    const float* dWih0   = (const float*)d_in[10];
    const float* dWhh0   = (const float*)d_in[11];
    const float* dbih0   = (const float*)d_in[12];
    const float* dbhh0   = (const float*)d_in[13];
    const float* dWih1   = (const float*)d_in[14];
    const float* dWhh1   = (const float*)d_in[15];
    const float* dbih1   = (const float*)d_in[16];
    const float* dbhh1   = (const float*)d_in[17];
    const float* fcW     = (const float*)d_in[18];
    const float* fcb     = (const float*)d_in[19];
    const float* recW    = (const float*)d_in[20];
    const float* recb    = (const float*)d_in[21];

    float* out = (float*)d_out;          // (64, 20)
    float* rec = out + 64 * 20;          // (64, 100, 10000)

    float *e, *gi, *y, *fcin;
    cudaGetSymbolAddress((void**)&e,    g_e);
    cudaGetSymbolAddress((void**)&gi,   g_gi);
    cudaGetSymbolAddress((void**)&y,    g_y);
    cudaGetSymbolAddress((void**)&fcin, g_fcin);

    dim3 gruGrid(BATCH, 2);

    // 1. embedding
    embed_kernel<<<6400, 128>>>(x, emb, e);

    // 2. encoder layer 0
    mma_tn<<<dim3(6, 50), 256>>>(e, 128, eWih0, ebih0, gi, 6400, 768, 128);
    gru_kernel<<<gruGrid, 384>>>(gi, TSEQ, 1, eWhh0, ebhh0, y, fcin + 0);

    // 3. encoder layer 1
    mma_tn<<<dim3(6, 50), 256>>>(y, 256, eWih1, ebih1, gi, 6400, 768, 256);
    gru_kernel<<<gruGrid, 384>>>(gi, TSEQ, 1, eWhh1, ebhh1, y, fcin + 256);

    // 4. decoder layer 0 (constant input over T: gi computed once per batch row)
    mma_tn<<<dim3(6, 1), 256>>>(fcin, 1024, dWih0, dbih0, gi, 64, 768, 512);
    gru_kernel<<<gruGrid, 384>>>(gi, 1, 0, dWhh0, dbhh0, y, fcin + 512);

    // 5. decoder layer 1 (output y = rec_seq)
    mma_tn<<<dim3(6, 50), 256>>>(y, 256, dWih1, dbih1, gi, 6400, 768, 256);
    gru_kernel<<<gruGrid, 384>>>(gi, TSEQ, 1, dWhh1, dbhh1, y, fcin + 768);

    // 6. classifier head (tiny, keep fp32): out = [enc_h, dec_h] @ fc_W^T + fc_b
    gemm_tn<<<dim3(1, 1), 256>>>(fcin, 1024, fcW, fcb, out, 64, 20, 1024);

    // 7. reconstruction (tf32 tensor cores): rec = rec_seq @ rec_W^T + rec_b
    mma_tn<<<dim3(79, 50), 256>>>(y, 256, recW, recb, rec, 6400, 10000, 256);
}

// round 8
// speedup vs baseline: 2.2824x; 1.1635x over previous
#include <cuda_runtime.h>
#include <math.h>

#define TSEQ 100
#define BATCH 64
#define HGRU  128
#define G3    384   // 3*H

// ---------------- tf32 helpers ----------------
__device__ __forceinline__ unsigned f2tf32(float x) {
    unsigned u;
    asm("cvt.rna.tf32.f32 %0, %1;" : "=r"(u) : "f"(x));
    return u;
}

__device__ __forceinline__ void mma_tf32v(float* d, const unsigned* a, const unsigned* b) {
    asm volatile(
        "mma.sync.aligned.m16n8k8.row.col.f32.tf32.tf32.f32 "
        "{%0,%1,%2,%3}, {%4,%5,%6,%7}, {%8,%9}, {%0,%1,%2,%3};"
        : "+f"(d[0]), "+f"(d[1]), "+f"(d[2]), "+f"(d[3])
        : "r"(a[0]), "r"(a[1]), "r"(a[2]), "r"(a[3]),
          "r"(b[0]), "r"(b[1]));
}

// cp.async helpers
#define CPA(dst, src, sz) \
    asm volatile("cp.async.ca.shared.global [%0], [%1], 16, %2;" :: "r"(dst), "l"(src), "r"(sz))
#define CPC()  asm volatile("cp.async.commit_group;")
#define CPW0() asm volatile("cp.async.wait_group 0;")
#define CPW1() asm volatile("cp.async.wait_group 1;")

// ---------------- scratch (static __device__, no allocation) ----------------
__device__ float g_e[6400 * 128];      // embedded input, tf32-rounded
__device__ float g_gi[6400 * 768];     // gi for both directions (fp32)
__device__ float g_y[6400 * 256];      // layer output, tf32-rounded
__device__ float g_fcin[64 * 1024];    // [enc_h(512) | dec_h(512)], full fp32
__device__ float g_fcin_tf[64 * 1024]; // tf32-rounded copy for dec-l0 GEMM
__device__ float g_wt[884736];         // tf32 Wih: enc0@0, enc1@98304, dec0@294912, dec1@688128
__device__ float g_recw[2560000];      // tf32 recW

// ---------------- elementwise tf32 rounding ----------------
__global__ void cvt_kernel(const float* __restrict__ src, float* __restrict__ dst, int n) {
    for (int i = blockIdx.x * 256 + threadIdx.x; i < n; i += gridDim.x * 256)
        dst[i] = __uint_as_float(f2tf32(src[i]));
}

// ---------------- embedding gather (writes tf32-rounded) ----------------
__global__ void embed_kernel(const int* __restrict__ x,
                             const float* __restrict__ emb,
                             float* __restrict__ e) {
    int row = blockIdx.x;                 // b*T + t
    int v = x[row];
    if (v > 9999) v = 9999;
    if (v < 0)    v = 0;
    e[row * 128 + threadIdx.x] = __uint_as_float(f2tf32(emb[v * 128 + threadIdx.x]));
}

// ---------------- small fp32 GEMM (classifier head only) ----------------
__global__ void gemm_tn(const float* __restrict__ A, int lda,
                        const float* __restrict__ W,
                        const float* __restrict__ bias,
                        float* __restrict__ C,
                        int M, int N, int K) {
    __shared__ float As[8][128];
    __shared__ float Ws[8][128];

    int t  = threadIdx.x;
    int tx = t & 15;
    int ty = t >> 4;
    int m0 = blockIdx.y * 128;
    int n0 = blockIdx.x * 128;
    int lr = t >> 1;
    int lk = (t & 1) * 4;

    float acc[8][8];
#pragma unroll
    for (int i = 0; i < 8; i++)
#pragma unroll
        for (int j = 0; j < 8; j++) acc[i][j] = 0.f;

    float4 aR = make_float4(0.f, 0.f, 0.f, 0.f);
    float4 wR = make_float4(0.f, 0.f, 0.f, 0.f);
    if (m0 + lr < M) aR = *(const float4*)&A[(size_t)(m0 + lr) * lda + 0 + lk];
    if (n0 + lr < N) wR = *(const float4*)&W[(size_t)(n0 + lr) * K + 0 + lk];

    for (int k0 = 0; k0 < K; k0 += 8) {
        As[lk + 0][lr] = aR.x; As[lk + 1][lr] = aR.y; As[lk + 2][lr] = aR.z; As[lk + 3][lr] = aR.w;
        Ws[lk + 0][lr] = wR.x; Ws[lk + 1][lr] = wR.y; Ws[lk + 2][lr] = wR.z; Ws[lk + 3][lr] = wR.w;
        __syncthreads();

        if (k0 + 8 < K) {
            aR = make_float4(0.f, 0.f, 0.f, 0.f);
            wR = make_float4(0.f, 0.f, 0.f, 0.f);
            if (m0 + lr < M) aR = *(const float4*)&A[(size_t)(m0 + lr) * lda + (k0 + 8) + lk];
            if (n0 + lr < N) wR = *(const float4*)&W[(size_t)(n0 + lr) * K + (k0 + 8) + lk];
        }

#pragma unroll
        for (int kk = 0; kk < 8; kk++) {
            float4 a0 = *(const float4*)&As[kk][ty * 4];
            float4 a1 = *(const float4*)&As[kk][64 + ty * 4];
            float4 b0 = *(const float4*)&Ws[kk][tx * 4];
            float4 b1 = *(const float4*)&Ws[kk][64 + tx * 4];
            float av[8] = {a0.x, a0.y, a0.z, a0.w, a1.x, a1.y, a1.z, a1.w};
            float bv[8] = {b0.x, b0.y, b0.z, b0.w, b1.x, b1.y, b1.z, b1.w};
#pragma unroll
            for (int i = 0; i < 8; i++)
#pragma unroll
                for (int j = 0; j < 8; j++) acc[i][j] += av[i] * bv[j];
        }
        __syncthreads();
    }

#pragma unroll
    for (int i = 0; i < 8; i++) {
        int m = m0 + ((i < 4) ? (ty * 4 + i) : (64 + ty * 4 + i - 4));
        if (m >= M) continue;
#pragma unroll
        for (int j = 0; j < 8; j++) {
            int n = n0 + ((j < 4) ? (tx * 4 + j) : (64 + tx * 4 + j - 4));
            if (n >= N) continue;
            C[(size_t)m * N + n] = acc[i][j] + bias[n];
        }
    }
}

// ---------------- GRU recurrence: Whh register-resident, one CTA per (b, dir) ----------------
__global__ void __launch_bounds__(384, 1)
gru_kernel(const float* __restrict__ gi_base, int rb, int rt,
           const float* __restrict__ Whh,   // (2, 384, 128)
           const float* __restrict__ bhh,   // (2, 384)
           float* __restrict__ y,           // (B, T, 256), written tf32-rounded
           float* __restrict__ hfin) {
    __shared__ float sh[128];
    __shared__ float sgh[G3];
    __shared__ float sgi[G3];

    int j   = threadIdx.x;    // 0..383
    int b   = blockIdx.x;
    int dir = blockIdx.y;

    const float* gi = gi_base + dir * G3;
    float bh = bhh[dir * G3 + j];

    float4 w[32];
    const float4* Wrow = (const float4*)(Whh + (dir * G3 + j) * HGRU);
#pragma unroll
    for (int kk = 0; kk < 32; kk++) w[kk] = Wrow[kk];

    if (j < HGRU) sh[j] = 0.f;
    __syncthreads();

    const float4* sh4 = (const float4*)sh;

    for (int t = 0; t < TSEQ; t++) {
        int tt  = dir ? (TSEQ - 1 - t) : t;
        int row = b * rb + tt * rt;
        float gval = gi[row * 768 + j];   // LDG overlaps FMA loop

        float acc0 = 0.f, acc1 = 0.f, acc2 = 0.f, acc3 = 0.f;
#pragma unroll
        for (int kk = 0; kk < 32; kk++) {
            float4 h4 = sh4[kk];
            acc0 += w[kk].x * h4.x;
            acc1 += w[kk].y * h4.y;
            acc2 += w[kk].z * h4.z;
            acc3 += w[kk].w * h4.w;
        }
        sgh[j] = (acc0 + acc1) + (acc2 + acc3) + bh;
        sgi[j] = gval;
        __syncthreads();

        if (j < HGRU) {
            float r = __fdividef(1.f, 1.f + __expf(-(sgi[j]        + sgh[j])));
            float z = __fdividef(1.f, 1.f + __expf(-(sgi[HGRU + j] + sgh[HGRU + j])));
            float nx = sgi[2 * HGRU + j] + r * sgh[2 * HGRU + j];
            float et = __expf(-2.f * nx);
            float n  = __fdividef(1.f - et, 1.f + et);   // tanh(nx)
            float hn = n + z * (sh[j] - n);
            sh[j] = hn;
            y[(b * TSEQ + tt) * 256 + dir * HGRU + j] = __uint_as_float(f2tf32(hn));
        }
        __syncthreads();
    }
    if (j < HGRU) hfin[b * 1024 + dir * HGRU + j] = sh[j];
}

// ---------------- tf32 MMA GEMM, cp.async double-buffered ----------------
// C[M,N] = A[M,K](lda) * W[N,K]^T + bias. Inputs MUST be pre-rounded to tf32.
// 128x128 CTA tile, 8 warps (4M x 2N), warp tile 32x64, K-chunk 32, 2-stage pipeline.
#define MMA_SMEM (2 * 128 * 36 * 4 * 2)   // 73728 B
__global__ void __launch_bounds__(256, 2)
mma_tn(const float* __restrict__ A, int lda,
       const float* __restrict__ W,     // (N, K)
       const float* __restrict__ bias,  // (N)
       float* __restrict__ C,
       int M, int N, int K) {
    extern __shared__ float smem[];
    float* As = smem;                    // [2][128][36]
    float* Bs = smem + 2 * 128 * 36;

    int t    = threadIdx.x;
    int lane = t & 31;
    int warp = t >> 5;
    int m0 = blockIdx.y * 128;
    int n0 = blockIdx.x * 128;
    int wm = (warp & 3) * 32;
    int wn = (warp >> 2) * 64;
    int r  = lane >> 2;       // 0..7
    int c  = lane & 3;        // 0..3

    unsigned sbaseA = (unsigned)__cvta_generic_to_shared(As);
    unsigned sbaseB = (unsigned)__cvta_generic_to_shared(Bs);

    float acc[2][8][4];
#pragma unroll
    for (int mf = 0; mf < 2; mf++)
#pragma unroll
        for (int nf = 0; nf < 8; nf++)
#pragma unroll
            for (int i = 0; i < 4; i++) acc[mf][nf][i] = 0.f;

    int nch = K >> 5;    // K/32 chunks (K is always a multiple of 32 here)

    auto stage = [&](int buf, int k0) {
#pragma unroll
        for (int i = 0; i < 4; i++) {
            int idx = i * 256 + t;
            int row = idx >> 3;
            int c4  = (idx & 7) * 4;
            unsigned off = ((unsigned)(buf * 128 + row) * 36 + c4) * 4;
            CPA(sbaseA + off, &A[(size_t)(m0 + row) * lda + k0 + c4], (m0 + row < M) ? 16 : 0);
            CPA(sbaseB + off, &W[(size_t)(n0 + row) * K   + k0 + c4], (n0 + row < N) ? 16 : 0);
        }
    };

    auto compute = [&](int buf) {
        const float* Ab = As + buf * 128 * 36;
        const float* Bb = Bs + buf * 128 * 36;
#pragma unroll
        for (int ks = 0; ks < 4; ks++) {
            int kb = ks * 8;
            unsigned a[2][4];
#pragma unroll
            for (int mf = 0; mf < 2; mf++) {
                int mr = wm + mf * 16 + r;
                a[mf][0] = __float_as_uint(Ab[(mr    ) * 36 + kb + c]);
                a[mf][1] = __float_as_uint(Ab[(mr + 8) * 36 + kb + c]);
                a[mf][2] = __float_as_uint(Ab[(mr    ) * 36 + kb + c + 4]);
                a[mf][3] = __float_as_uint(Ab[(mr + 8) * 36 + kb + c + 4]);
            }
#pragma unroll
            for (int nf = 0; nf < 8; nf++) {
                int nr = wn + nf * 8 + r;
                unsigned b[2];
                b[0] = __float_as_uint(Bb[nr * 36 + kb + c]);
                b[1] = __float_as_uint(Bb[nr * 36 + kb + c + 4]);
                mma_tf32v(acc[0][nf], a[0], b);
                mma_tf32v(acc[1][nf], a[1], b);
            }
        }
    };

    // prologue: 2 chunks in flight
    stage(0, 0);  CPC();
    stage(1, 32); CPC();

    for (int ci = 0; ci < nch; ci++) {
        if (ci < nch - 1) { CPW1(); } else { CPW0(); }
        __syncthreads();
        compute(ci & 1);
        __syncthreads();
        if (ci + 2 < nch) { stage(ci & 1, (ci + 2) * 32); CPC(); }
    }

    // epilogue
#pragma unroll
    for (int mf = 0; mf < 2; mf++) {
#pragma unroll
        for (int nf = 0; nf < 8; nf++) {
            int n = n0 + wn + nf * 8 + 2 * c;
            if (n >= N) continue;
            float bv0 = bias[n];
            float bv1 = bias[n + 1];
            int m = m0 + wm + mf * 16 + r;
            if (m < M) {
                *(float2*)&C[(size_t)m * N + n] =
                    make_float2(acc[mf][nf][0] + bv0, acc[mf][nf][1] + bv1);
            }
            if (m + 8 < M) {
                *(float2*)&C[(size_t)(m + 8) * N + n] =
                    make_float2(acc[mf][nf][2] + bv0, acc[mf][nf][3] + bv1);
            }
        }
    }
}

// ---------------- driver ----------------
extern "C" void kernel_launch(void* const* d_in, const int* in_sizes, int n_in,
                              void* d_out, int out_size) {
    const int* x         = (const int*)d_in[0];
    const float* emb     = (const float*)d_in[1];
    const float* eWih0   = (const float*)d_in[2];
    const float* eWhh0   = (const float*)d_in[3];
    const float* ebih0   = (const float*)d_in[4];
    const float* ebhh0   = (const float*)d_in[5];
    const float* eWih1   = (const float*)d_in[6];
    const float* eWhh1   = (const float*)d_in[7];
    const float* ebih1   = (const float*)d_in[8];
    const float* ebhh1   = (const float*)d_in[9];
    const float* dWih0   = (const float*)d_in[10];
    const float* dWhh0   = (const float*)d_in[11];
    const float* dbih0   = (const float*)d_in[12];
    const float* dbhh0   = (const float*)d_in[13];
    const float* dWih1   = (const float*)d_in[14];
    const float* dWhh1   = (const float*)d_in[15];
    const float* dbih1   = (const float*)d_in[16];
    const float* dbhh1   = (const float*)d_in[17];
    const float* fcW     = (const float*)d_in[18];
    const float* fcb     = (const float*)d_in[19];
    const float* recW    = (const float*)d_in[20];
    const float* recb    = (const float*)d_in[21];

    float* out = (float*)d_out;          // (64, 20)
    float* rec = out + 64 * 20;          // (64, 100, 10000)

    float *e, *gi, *y, *fcin, *fcin_tf, *wt, *recw;
    cudaGetSymbolAddress((void**)&e,       g_e);
    cudaGetSymbolAddress((void**)&gi,      g_gi);
    cudaGetSymbolAddress((void**)&y,       g_y);
    cudaGetSymbolAddress((void**)&fcin,    g_fcin);
    cudaGetSymbolAddress((void**)&fcin_tf, g_fcin_tf);
    cudaGetSymbolAddress((void**)&wt,      g_wt);
    cudaGetSymbolAddress((void**)&recw,    g_recw);

    cudaFuncSetAttribute(mma_tn, cudaFuncAttributeMaxDynamicSharedMemorySize, MMA_SMEM);

    dim3 gruGrid(BATCH, 2);

    // 0. pre-round weights to tf32 (scratch)
    cvt_kernel<<<96,  256>>>(eWih0, wt + 0,      98304);
    cvt_kernel<<<192, 256>>>(eWih1, wt + 98304,  196608);
    cvt_kernel<<<384, 256>>>(dWih0, wt + 294912, 393216);
    cvt_kernel<<<192, 256>>>(dWih1, wt + 688128, 196608);
    cvt_kernel<<<2500,256>>>(recW,  recw,        2560000);

    // 1. embedding (tf32-rounded output)
    embed_kernel<<<6400, 128>>>(x, emb, e);

    // 2. encoder layer 0
    mma_tn<<<dim3(6, 50), 256, MMA_SMEM>>>(e, 128, wt + 0, ebih0, gi, 6400, 768, 128);
    gru_kernel<<<gruGrid, 384>>>(gi, TSEQ, 1, eWhh0, ebhh0, y, fcin + 0);

    // 3. encoder layer 1
    mma_tn<<<dim3(6, 50), 256, MMA_SMEM>>>(y, 256, wt + 98304, ebih1, gi, 6400, 768, 256);
    gru_kernel<<<gruGrid, 384>>>(gi, TSEQ, 1, eWhh1, ebhh1, y, fcin + 256);

    // 4. decoder layer 0 (constant input over T)
    cvt_kernel<<<64, 256>>>(fcin, fcin_tf, 65536);
    mma_tn<<<dim3(6, 1), 256, MMA_SMEM>>>(fcin_tf, 1024, wt + 294912, dbih0, gi, 64, 768, 512);
    gru_kernel<<<gruGrid, 384>>>(gi, 1, 0, dWhh0, dbhh0, y, fcin + 512);

    // 5. decoder layer 1 (output y = rec_seq)
    mma_tn<<<dim3(6, 50), 256, MMA_SMEM>>>(y, 256, wt + 688128, dbih1, gi, 6400, 768, 256);
    gru_kernel<<<gruGrid, 384>>>(gi, TSEQ, 1, dWhh1, dbhh1, y, fcin + 768);

    // 6. classifier head (fp32, full-precision fcin)
    gemm_tn<<<dim3(1, 1), 256>>>(fcin, 1024, fcW, fcb, out, 64, 20, 1024);

    // 7. reconstruction: rec = rec_seq @ rec_W^T + rec_b
    mma_tn<<<dim3(79, 50), 256, MMA_SMEM>>>(y, 256, recw, recb, rec, 6400, 10000, 256);
}

// round 10
// speedup vs baseline: 2.6827x; 1.1754x over previous
#include <cuda_runtime.h>
#include <math.h>

#define TSEQ 100
#define BATCH 64
#define HGRU  128
#define G3    384   // 3*H

// ---------------- tf32 helpers ----------------
__device__ __forceinline__ unsigned f2tf32(float x) {
    unsigned u;
    asm("cvt.rna.tf32.f32 %0, %1;" : "=r"(u) : "f"(x));
    return u;
}

__device__ __forceinline__ void mma_tf32v(float* d, const unsigned* a, const unsigned* b) {
    asm volatile(
        "mma.sync.aligned.m16n8k8.row.col.f32.tf32.tf32.f32 "
        "{%0,%1,%2,%3}, {%4,%5,%6,%7}, {%8,%9}, {%0,%1,%2,%3};"
        : "+f"(d[0]), "+f"(d[1]), "+f"(d[2]), "+f"(d[3])
        : "r"(a[0]), "r"(a[1]), "r"(a[2]), "r"(a[3]),
          "r"(b[0]), "r"(b[1]));
}

// cp.async helpers
#define CPA(dst, src, sz) \
    asm volatile("cp.async.ca.shared.global [%0], [%1], 16, %2;" :: "r"(dst), "l"(src), "r"(sz))
#define CPC()  asm volatile("cp.async.commit_group;")
#define CPW0() asm volatile("cp.async.wait_group 0;")
#define CPW1() asm volatile("cp.async.wait_group 1;")

// ---------------- scratch (static __device__, no allocation) ----------------
__device__ float g_e[6400 * 128];      // embedded input, tf32-rounded
__device__ float g_gi[6400 * 768];     // gi for both directions (fp32)
__device__ float g_y[6400 * 256];      // layer output, tf32-rounded
__device__ float g_fcin[64 * 1024];    // [enc_h(512) | dec_h(512)], full fp32
__device__ float g_fcin_tf[64 * 1024]; // tf32-rounded copy for dec-l0 GEMM
__device__ float g_wt[884736];         // tf32 Wih: enc0@0, enc1@98304, dec0@294912, dec1@688128
__device__ float g_recw[2560000];      // tf32 recW

// ---------------- fused tf32 rounding of all 5 weight regions (one launch) ----------------
// float4 units: 24576 | 49152 | 98304 | 49152 | 640000, prefix: 24576,73728,172032,221184,861184
__global__ void cvt_all(const float4* __restrict__ s0, float4* __restrict__ d0,
                        const float4* __restrict__ s1, float4* __restrict__ d1,
                        const float4* __restrict__ s2, float4* __restrict__ d2,
                        const float4* __restrict__ s3, float4* __restrict__ d3,
                        const float4* __restrict__ s4, float4* __restrict__ d4) {
    int i = blockIdx.x * 256 + threadIdx.x;
    const float4* s; float4* d; int off;
    if      (i < 24576)  { s = s0; d = d0; off = i; }
    else if (i < 73728)  { s = s1; d = d1; off = i - 24576; }
    else if (i < 172032) { s = s2; d = d2; off = i - 73728; }
    else if (i < 221184) { s = s3; d = d3; off = i - 172032; }
    else if (i < 861184) { s = s4; d = d4; off = i - 221184; }
    else return;
    float4 v = s[off];
    v.x = __uint_as_float(f2tf32(v.x));
    v.y = __uint_as_float(f2tf32(v.y));
    v.z = __uint_as_float(f2tf32(v.z));
    v.w = __uint_as_float(f2tf32(v.w));
    d[off] = v;
}

// ---------------- elementwise tf32 rounding (fcin only) ----------------
__global__ void cvt_kernel(const float* __restrict__ src, float* __restrict__ dst, int n) {
    for (int i = blockIdx.x * 256 + threadIdx.x; i < n; i += gridDim.x * 256)
        dst[i] = __uint_as_float(f2tf32(src[i]));
}

// ---------------- embedding gather (writes tf32-rounded) ----------------
__global__ void embed_kernel(const int* __restrict__ x,
                             const float* __restrict__ emb,
                             float* __restrict__ e) {
    int row = blockIdx.x;                 // b*T + t
    int v = x[row];
    if (v > 9999) v = 9999;
    if (v < 0)    v = 0;
    e[row * 128 + threadIdx.x] = __uint_as_float(f2tf32(emb[v * 128 + threadIdx.x]));
}

// ---------------- classifier head GEMV: warp per output ----------------
__global__ void fc_kernel(const float* __restrict__ fcin,   // (64, 1024)
                          const float* __restrict__ W,      // (20, 1024)
                          const float* __restrict__ bias,   // (20)
                          float* __restrict__ out) {        // (64, 20)
    int wid  = (blockIdx.x * blockDim.x + threadIdx.x) >> 5;
    int lane = threadIdx.x & 31;
    if (wid >= 64 * 20) return;
    int m = wid / 20, n = wid % 20;
    const float4* a = (const float4*)(fcin + m * 1024);
    const float4* w = (const float4*)(W    + n * 1024);
    float s = 0.f;
#pragma unroll
    for (int i = lane; i < 256; i += 32) {
        float4 x = a[i], y = w[i];
        s += x.x * y.x + x.y * y.y + x.z * y.z + x.w * y.w;
    }
#pragma unroll
    for (int o = 16; o; o >>= 1) s += __shfl_xor_sync(0xffffffffu, s, o);
    if (lane == 0) out[m * 20 + n] = s + bias[n];
}

// ---------------- GRU recurrence: packed f32x2 FMA, Whh register-resident ----------------
// h loads are COMPILER-VISIBLE shared reads (not asm) so they cannot be hoisted
// across __syncthreads(); only the FMA itself is asm (inputs vary per iter -> no CSE).
__global__ void __launch_bounds__(384, 1)
gru_kernel(const float* __restrict__ gi_base, int rb, int rt,
           const float* __restrict__ Whh,   // (2, 384, 128)
           const float* __restrict__ bhh,   // (2, 384)
           float* __restrict__ y,           // (B, T, 256), written tf32-rounded
           float* __restrict__ hfin) {
    __shared__ __align__(16) float sh[128];
    __shared__ float sgh[G3];
    __shared__ float sgi[G3];

    int j   = threadIdx.x;    // 0..383 (gate-column)
    int b   = blockIdx.x;
    int dir = blockIdx.y;

    const float* gi = gi_base + dir * G3;
    float bh = bhh[dir * G3 + j];

    // this column's Whh row (128 floats) as 64 packed f32x2 registers
    unsigned long long w2[64];
    const unsigned long long* Wrow =
        (const unsigned long long*)(Whh + (size_t)(dir * G3 + j) * HGRU);
#pragma unroll
    for (int kk = 0; kk < 64; kk++) w2[kk] = Wrow[kk];

    if (j < HGRU) sh[j] = 0.f;
    __syncthreads();

    const unsigned long long* sh2 = (const unsigned long long*)sh;

    for (int t = 0; t < TSEQ; t++) {
        int tt  = dir ? (TSEQ - 1 - t) : t;
        int row = b * rb + tt * rt;
        float gval = gi[row * 768 + j];   // LDG overlaps FMA loop

        unsigned long long acc0 = 0ULL, acc1 = 0ULL, acc2 = 0ULL, acc3 = 0ULL;
#pragma unroll
        for (int kk = 0; kk < 64; kk += 4) {
            unsigned long long h0 = sh2[kk + 0];
            unsigned long long h1 = sh2[kk + 1];
            unsigned long long h2 = sh2[kk + 2];
            unsigned long long h3 = sh2[kk + 3];
            asm("fma.rn.f32x2 %0, %1, %2, %0;" : "+l"(acc0) : "l"(w2[kk + 0]), "l"(h0));
            asm("fma.rn.f32x2 %0, %1, %2, %0;" : "+l"(acc1) : "l"(w2[kk + 1]), "l"(h1));
            asm("fma.rn.f32x2 %0, %1, %2, %0;" : "+l"(acc2) : "l"(w2[kk + 2]), "l"(h2));
            asm("fma.rn.f32x2 %0, %1, %2, %0;" : "+l"(acc3) : "l"(w2[kk + 3]), "l"(h3));
        }
        asm("add.rn.f32x2 %0, %0, %1;" : "+l"(acc0) : "l"(acc1));
        asm("add.rn.f32x2 %0, %0, %1;" : "+l"(acc2) : "l"(acc3));
        asm("add.rn.f32x2 %0, %0, %1;" : "+l"(acc0) : "l"(acc2));
        float lo, hi;
        asm("mov.b64 {%0,%1}, %2;" : "=f"(lo), "=f"(hi) : "l"(acc0));

        sgh[j] = lo + hi + bh;
        sgi[j] = gval;
        __syncthreads();

        if (j < HGRU) {
            float r = __fdividef(1.f, 1.f + __expf(-(sgi[j]        + sgh[j])));
            float z = __fdividef(1.f, 1.f + __expf(-(sgi[HGRU + j] + sgh[HGRU + j])));
            float nx = sgi[2 * HGRU + j] + r * sgh[2 * HGRU + j];
            float et = __expf(-2.f * nx);
            float n  = __fdividef(1.f - et, 1.f + et);   // tanh(nx)
            float hn = n + z * (sh[j] - n);
            sh[j] = hn;
            y[(b * TSEQ + tt) * 256 + dir * HGRU + j] = __uint_as_float(f2tf32(hn));
        }
        __syncthreads();
    }
    if (j < HGRU) hfin[b * 1024 + dir * HGRU + j] = sh[j];
}

// ---------------- tf32 MMA GEMM, cp.async double-buffered ----------------
// C[M,N] = A[M,K](lda) * W[N,K]^T + bias. Inputs MUST be pre-rounded to tf32.
// 128x128 CTA tile, 8 warps (4M x 2N), warp tile 32x64, K-chunk 32, 2-stage pipeline.
#define MMA_SMEM (2 * 128 * 36 * 4 * 2)   // 73728 B
__global__ void __launch_bounds__(256, 2)
mma_tn(const float* __restrict__ A, int lda,
       const float* __restrict__ W,     // (N, K)
       const float* __restrict__ bias,  // (N)
       float* __restrict__ C,
       int M, int N, int K) {
    extern __shared__ float smem[];
    float* As = smem;                    // [2][128][36]
    float* Bs = smem + 2 * 128 * 36;

    int t    = threadIdx.x;
    int lane = t & 31;
    int warp = t >> 5;
    int m0 = blockIdx.y * 128;
    int n0 = blockIdx.x * 128;
    int wm = (warp & 3) * 32;
    int wn = (warp >> 2) * 64;
    int r  = lane >> 2;       // 0..7
    int c  = lane & 3;        // 0..3

    unsigned sbaseA = (unsigned)__cvta_generic_to_shared(As);
    unsigned sbaseB = (unsigned)__cvta_generic_to_shared(Bs);

    float acc[2][8][4];
#pragma unroll
    for (int mf = 0; mf < 2; mf++)
#pragma unroll
        for (int nf = 0; nf < 8; nf++)
#pragma unroll
            for (int i = 0; i < 4; i++) acc[mf][nf][i] = 0.f;

    int nch = K >> 5;    // K/32 chunks

    auto stage = [&](int buf, int k0) {
#pragma unroll
        for (int i = 0; i < 4; i++) {
            int idx = i * 256 + t;
            int row = idx >> 3;
            int c4  = (idx & 7) * 4;
            unsigned off = ((unsigned)(buf * 128 + row) * 36 + c4) * 4;
            CPA(sbaseA + off, &A[(size_t)(m0 + row) * lda + k0 + c4], (m0 + row < M) ? 16 : 0);
            CPA(sbaseB + off, &W[(size_t)(n0 + row) * K   + k0 + c4], (n0 + row < N) ? 16 : 0);
        }
    };

    auto compute = [&](int buf) {
        const float* Ab = As + buf * 128 * 36;
        const float* Bb = Bs + buf * 128 * 36;
#pragma unroll
        for (int ks = 0; ks < 4; ks++) {
            int kb = ks * 8;
            unsigned a[2][4];
#pragma unroll
            for (int mf = 0; mf < 2; mf++) {
                int mr = wm + mf * 16 + r;
                a[mf][0] = __float_as_uint(Ab[(mr    ) * 36 + kb + c]);
                a[mf][1] = __float_as_uint(Ab[(mr + 8) * 36 + kb + c]);
                a[mf][2] = __float_as_uint(Ab[(mr    ) * 36 + kb + c + 4]);
                a[mf][3] = __float_as_uint(Ab[(mr + 8) * 36 + kb + c + 4]);
            }
#pragma unroll
            for (int nf = 0; nf < 8; nf++) {
                int nr = wn + nf * 8 + r;
                unsigned b[2];
                b[0] = __float_as_uint(Bb[nr * 36 + kb + c]);
                b[1] = __float_as_uint(Bb[nr * 36 + kb + c + 4]);
                mma_tf32v(acc[0][nf], a[0], b);
                mma_tf32v(acc[1][nf], a[1], b);
            }
        }
    };

    // prologue: 2 chunks in flight
    stage(0, 0);  CPC();
    stage(1, 32); CPC();

    for (int ci = 0; ci < nch; ci++) {
        if (ci < nch - 1) { CPW1(); } else { CPW0(); }
        __syncthreads();
        compute(ci & 1);
        __syncthreads();
        if (ci + 2 < nch) { stage(ci & 1, (ci + 2) * 32); CPC(); }
    }

    // epilogue
#pragma unroll
    for (int mf = 0; mf < 2; mf++) {
#pragma unroll
        for (int nf = 0; nf < 8; nf++) {
            int n = n0 + wn + nf * 8 + 2 * c;
            if (n >= N) continue;
            float bv0 = bias[n];
            float bv1 = bias[n + 1];
            int m = m0 + wm + mf * 16 + r;
            if (m < M) {
                *(float2*)&C[(size_t)m * N + n] =
                    make_float2(acc[mf][nf][0] + bv0, acc[mf][nf][1] + bv1);
            }
            if (m + 8 < M) {
                *(float2*)&C[(size_t)(m + 8) * N + n] =
                    make_float2(acc[mf][nf][2] + bv0, acc[mf][nf][3] + bv1);
            }
        }
    }
}

// ---------------- driver ----------------
extern "C" void kernel_launch(void* const* d_in, const int* in_sizes, int n_in,
                              void* d_out, int out_size) {
    const int* x         = (const int*)d_in[0];
    const float* emb     = (const float*)d_in[1];
    const float* eWih0   = (const float*)d_in[2];
    const float* eWhh0   = (const float*)d_in[3];
    const float* ebih0   = (const float*)d_in[4];
    const float* ebhh0   = (const float*)d_in[5];
    const float* eWih1   = (const float*)d_in[6];
    const float* eWhh1   = (const float*)d_in[7];
    const float* ebih1   = (const float*)d_in[8];
    const float* ebhh1   = (const float*)d_in[9];
    const float* dWih0   = (const float*)d_in[10];
    const float* dWhh0   = (const float*)d_in[11];
    const float* dbih0   = (const float*)d_in[12];
    const float* dbhh0   = (const float*)d_in[13];
    const float* dWih1   = (const float*)d_in[14];
    const float* dWhh1   = (const float*)d_in[15];
    const float* dbih1   = (const float*)d_in[16];
    const float* dbhh1   = (const float*)d_in[17];
    const float* fcW     = (const float*)d_in[18];
    const float* fcb     = (const float*)d_in[19];
    const float* recW    = (const float*)d_in[20];
    const float* recb    = (const float*)d_in[21];

    float* out = (float*)d_out;          // (64, 20)
    float* rec = out + 64 * 20;          // (64, 100, 10000)

    float *e, *gi, *y, *fcin, *fcin_tf, *wt, *recw;
    cudaGetSymbolAddress((void**)&e,       g_e);
    cudaGetSymbolAddress((void**)&gi,      g_gi);
    cudaGetSymbolAddress((void**)&y,       g_y);
    cudaGetSymbolAddress((void**)&fcin,    g_fcin);
    cudaGetSymbolAddress((void**)&fcin_tf, g_fcin_tf);
    cudaGetSymbolAddress((void**)&wt,      g_wt);
    cudaGetSymbolAddress((void**)&recw,    g_recw);

    cudaFuncSetAttribute(mma_tn, cudaFuncAttributeMaxDynamicSharedMemorySize, MMA_SMEM);

    dim3 gruGrid(BATCH, 2);

    // 0. pre-round all GEMM weights to tf32, one launch
    cvt_all<<<3364, 256>>>((const float4*)eWih0, (float4*)(wt + 0),
                           (const float4*)eWih1, (float4*)(wt + 98304),
                           (const float4*)dWih0, (float4*)(wt + 294912),
                           (const float4*)dWih1, (float4*)(wt + 688128),
                           (const float4*)recW,  (float4*)recw);

    // 1. embedding (tf32-rounded output)
    embed_kernel<<<6400, 128>>>(x, emb, e);

    // 2. encoder layer 0
    mma_tn<<<dim3(6, 50), 256, MMA_SMEM>>>(e, 128, wt + 0, ebih0, gi, 6400, 768, 128);
    gru_kernel<<<gruGrid, 384>>>(gi, TSEQ, 1, eWhh0, ebhh0, y, fcin + 0);

    // 3. encoder layer 1
    mma_tn<<<dim3(6, 50), 256, MMA_SMEM>>>(y, 256, wt + 98304, ebih1, gi, 6400, 768, 256);
    gru_kernel<<<gruGrid, 384>>>(gi, TSEQ, 1, eWhh1, ebhh1, y, fcin + 256);

    // 4. decoder layer 0 (constant input over T)
    cvt_kernel<<<64, 256>>>(fcin, fcin_tf, 65536);
    mma_tn<<<dim3(6, 1), 256, MMA_SMEM>>>(fcin_tf, 1024, wt + 294912, dbih0, gi, 64, 768, 512);
    gru_kernel<<<gruGrid, 384>>>(gi, 1, 0, dWhh0, dbhh0, y, fcin + 512);

    // 5. decoder layer 1 (output y = rec_seq)
    mma_tn<<<dim3(6, 50), 256, MMA_SMEM>>>(y, 256, wt + 688128, dbih1, gi, 6400, 768, 256);
    gru_kernel<<<gruGrid, 384>>>(gi, TSEQ, 1, dWhh1, dbhh1, y, fcin + 768);

    // 6. classifier head (fp32 GEMV, warp per output)
    fc_kernel<<<160, 256>>>(fcin, fcW, fcb, out);

    // 7. reconstruction: rec = rec_seq @ rec_W^T + rec_b
    mma_tn<<<dim3(79, 50), 256, MMA_SMEM>>>(y, 256, recw, recb, rec, 6400, 10000, 256);
}

// round 11
// speedup vs baseline: 2.7351x; 1.0195x over previous
#include <cuda_runtime.h>
#include <math.h>

#define TSEQ 100
#define BATCH 64
#define HGRU  128
#define G3    384   // 3*H

// ---------------- tf32 helpers ----------------
__device__ __forceinline__ unsigned f2tf32(float x) {
    unsigned u;
    asm("cvt.rna.tf32.f32 %0, %1;" : "=r"(u) : "f"(x));
    return u;
}

__device__ __forceinline__ void mma_tf32v(float* d, const unsigned* a, const unsigned* b) {
    asm volatile(
        "mma.sync.aligned.m16n8k8.row.col.f32.tf32.tf32.f32 "
        "{%0,%1,%2,%3}, {%4,%5,%6,%7}, {%8,%9}, {%0,%1,%2,%3};"
        : "+f"(d[0]), "+f"(d[1]), "+f"(d[2]), "+f"(d[3])
        : "r"(a[0]), "r"(a[1]), "r"(a[2]), "r"(a[3]),
          "r"(b[0]), "r"(b[1]));
}

// cp.async helpers
#define CPA(dst, src, sz) \
    asm volatile("cp.async.ca.shared.global [%0], [%1], 16, %2;" :: "r"(dst), "l"(src), "r"(sz))
#define CPC()  asm volatile("cp.async.commit_group;")
#define CPW0() asm volatile("cp.async.wait_group 0;")
#define CPW1() asm volatile("cp.async.wait_group 1;")

// ---------------- scratch (static __device__, no allocation) ----------------
__device__ float g_e[6400 * 128];      // embedded input, tf32-rounded
__device__ float g_gi[6400 * 768];     // gi for both directions (fp32)
__device__ float g_y[6400 * 256];      // layer output, tf32-rounded
__device__ float g_fcin[64 * 1024];    // [enc_h(512) | dec_h(512)], full fp32
__device__ float g_fcin_tf[64 * 1024]; // tf32-rounded copy for dec-l0 GEMM
__device__ float g_wt[884736];         // tf32 Wih: enc0@0, enc1@98304, dec0@294912, dec1@688128
__device__ float g_recw[2560000];      // tf32 recW

// ---------------- fused tf32 rounding of all 5 weight regions (one launch) ----------------
// float4 units: 24576 | 49152 | 98304 | 49152 | 640000, prefix: 24576,73728,172032,221184,861184
__global__ void cvt_all(const float4* __restrict__ s0, float4* __restrict__ d0,
                        const float4* __restrict__ s1, float4* __restrict__ d1,
                        const float4* __restrict__ s2, float4* __restrict__ d2,
                        const float4* __restrict__ s3, float4* __restrict__ d3,
                        const float4* __restrict__ s4, float4* __restrict__ d4) {
    int i = blockIdx.x * 256 + threadIdx.x;
    const float4* s; float4* d; int off;
    if      (i < 24576)  { s = s0; d = d0; off = i; }
    else if (i < 73728)  { s = s1; d = d1; off = i - 24576; }
    else if (i < 172032) { s = s2; d = d2; off = i - 73728; }
    else if (i < 221184) { s = s3; d = d3; off = i - 172032; }
    else if (i < 861184) { s = s4; d = d4; off = i - 221184; }
    else return;
    float4 v = s[off];
    v.x = __uint_as_float(f2tf32(v.x));
    v.y = __uint_as_float(f2tf32(v.y));
    v.z = __uint_as_float(f2tf32(v.z));
    v.w = __uint_as_float(f2tf32(v.w));
    d[off] = v;
}

// ---------------- elementwise tf32 rounding (fcin only) ----------------
__global__ void cvt_kernel(const float* __restrict__ src, float* __restrict__ dst, int n) {
    for (int i = blockIdx.x * 256 + threadIdx.x; i < n; i += gridDim.x * 256)
        dst[i] = __uint_as_float(f2tf32(src[i]));
}

// ---------------- embedding gather (writes tf32-rounded) ----------------
__global__ void embed_kernel(const int* __restrict__ x,
                             const float* __restrict__ emb,
                             float* __restrict__ e) {
    int row = blockIdx.x;                 // b*T + t
    int v = x[row];
    if (v > 9999) v = 9999;
    if (v < 0)    v = 0;
    e[row * 128 + threadIdx.x] = __uint_as_float(f2tf32(emb[v * 128 + threadIdx.x]));
}

// ---------------- classifier head GEMV: warp per output ----------------
__global__ void fc_kernel(const float* __restrict__ fcin,   // (64, 1024)
                          const float* __restrict__ W,      // (20, 1024)
                          const float* __restrict__ bias,   // (20)
                          float* __restrict__ out) {        // (64, 20)
    int wid  = (blockIdx.x * blockDim.x + threadIdx.x) >> 5;
    int lane = threadIdx.x & 31;
    if (wid >= 64 * 20) return;
    int m = wid / 20, n = wid % 20;
    const float4* a = (const float4*)(fcin + m * 1024);
    const float4* w = (const float4*)(W    + n * 1024);
    float s = 0.f;
#pragma unroll
    for (int i = lane; i < 256; i += 32) {
        float4 x = a[i], y = w[i];
        s += x.x * y.x + x.y * y.y + x.z * y.z + x.w * y.w;
    }
#pragma unroll
    for (int o = 16; o; o >>= 1) s += __shfl_xor_sync(0xffffffffu, s, o);
    if (lane == 0) out[m * 20 + n] = s + bias[n];
}

// ---------------- GRU recurrence: packed f32x2 FMA, LDS.128 h-loads, gi prefetch ----------------
// h loads are COMPILER-VISIBLE shared reads so they cannot be hoisted across
// __syncthreads(); only the FMA is asm (inputs vary per iteration -> no CSE).
__global__ void __launch_bounds__(384, 1)
gru_kernel(const float* __restrict__ gi_base, int rb, int rt,
           const float* __restrict__ Whh,   // (2, 384, 128)
           const float* __restrict__ bhh,   // (2, 384)
           float* __restrict__ y,           // (B, T, 256), written tf32-rounded
           float* __restrict__ hfin) {
    __shared__ __align__(16) float sh[128];
    __shared__ float sgh[G3];
    __shared__ float sgi[G3];

    int j   = threadIdx.x;    // 0..383 (gate-column)
    int b   = blockIdx.x;
    int dir = blockIdx.y;

    const float* gi = gi_base + dir * G3;
    float bh = bhh[dir * G3 + j];

    // this column's Whh row (128 floats) as 64 packed f32x2 registers
    unsigned long long w2[64];
    const unsigned long long* Wrow =
        (const unsigned long long*)(Whh + (size_t)(dir * G3 + j) * HGRU);
#pragma unroll
    for (int kk = 0; kk < 64; kk++) w2[kk] = Wrow[kk];

    if (j < HGRU) sh[j] = 0.f;
    __syncthreads();

    const ulonglong2* sh2 = (const ulonglong2*)sh;   // 32 x 16B

    // prefetch gi for t=0
    {
        int tt0 = dir ? (TSEQ - 1) : 0;
        // fallthrough into loop's gval
    }
    int tt_first = dir ? (TSEQ - 1) : 0;
    float gval = gi[(b * rb + tt_first * rt) * 768 + j];

    for (int t = 0; t < TSEQ; t++) {
        int tt = dir ? (TSEQ - 1 - t) : t;

        // prefetch next step's gi — consumed a full step later
        float gnext = 0.f;
        if (t + 1 < TSEQ) {
            int ttn = dir ? (TSEQ - 2 - t) : (t + 1);
            gnext = gi[(b * rb + ttn * rt) * 768 + j];
        }

        unsigned long long acc0 = 0ULL, acc1 = 0ULL, acc2 = 0ULL, acc3 = 0ULL;
#pragma unroll
        for (int kk = 0; kk < 32; kk += 2) {
            ulonglong2 ha = sh2[kk];
            ulonglong2 hb = sh2[kk + 1];
            asm("fma.rn.f32x2 %0, %1, %2, %0;" : "+l"(acc0) : "l"(w2[2 * kk + 0]), "l"(ha.x));
            asm("fma.rn.f32x2 %0, %1, %2, %0;" : "+l"(acc1) : "l"(w2[2 * kk + 1]), "l"(ha.y));
            asm("fma.rn.f32x2 %0, %1, %2, %0;" : "+l"(acc2) : "l"(w2[2 * kk + 2]), "l"(hb.x));
            asm("fma.rn.f32x2 %0, %1, %2, %0;" : "+l"(acc3) : "l"(w2[2 * kk + 3]), "l"(hb.y));
        }
        asm("add.rn.f32x2 %0, %0, %1;" : "+l"(acc0) : "l"(acc1));
        asm("add.rn.f32x2 %0, %0, %1;" : "+l"(acc2) : "l"(acc3));
        asm("add.rn.f32x2 %0, %0, %1;" : "+l"(acc0) : "l"(acc2));
        float lo, hi;
        asm("mov.b64 {%0,%1}, %2;" : "=f"(lo), "=f"(hi) : "l"(acc0));

        sgh[j] = lo + hi + bh;
        sgi[j] = gval;
        __syncthreads();

        if (j < HGRU) {
            float r = __fdividef(1.f, 1.f + __expf(-(sgi[j]        + sgh[j])));
            float z = __fdividef(1.f, 1.f + __expf(-(sgi[HGRU + j] + sgh[HGRU + j])));
            float nx = sgi[2 * HGRU + j] + r * sgh[2 * HGRU + j];
            float et = __expf(-2.f * nx);
            float n  = __fdividef(1.f - et, 1.f + et);   // tanh(nx)
            float hn = n + z * (sh[j] - n);
            sh[j] = hn;
            y[(b * TSEQ + tt) * 256 + dir * HGRU + j] = __uint_as_float(f2tf32(hn));
        }
        __syncthreads();

        gval = gnext;
    }
    if (j < HGRU) hfin[b * 1024 + dir * HGRU + j] = sh[j];
}

// ---------------- tf32 MMA GEMM, cp.async double-buffered ----------------
// C[M,N] = A[M,K](lda) * W[N,K]^T + bias. Inputs MUST be pre-rounded to tf32.
// 128x128 CTA tile, 8 warps (4M x 2N), warp tile 32x64, K-chunk 32, 2-stage pipeline.
#define MMA_SMEM (2 * 128 * 36 * 4 * 2)   // 73728 B
__global__ void __launch_bounds__(256, 2)
mma_tn(const float* __restrict__ A, int lda,
       const float* __restrict__ W,     // (N, K)
       const float* __restrict__ bias,  // (N)
       float* __restrict__ C,
       int M, int N, int K) {
    extern __shared__ float smem[];
    float* As = smem;                    // [2][128][36]
    float* Bs = smem + 2 * 128 * 36;

    int t    = threadIdx.x;
    int lane = t & 31;
    int warp = t >> 5;
    int m0 = blockIdx.y * 128;
    int n0 = blockIdx.x * 128;
    int wm = (warp & 3) * 32;
    int wn = (warp >> 2) * 64;
    int r  = lane >> 2;       // 0..7
    int c  = lane & 3;        // 0..3

    unsigned sbaseA = (unsigned)__cvta_generic_to_shared(As);
    unsigned sbaseB = (unsigned)__cvta_generic_to_shared(Bs);

    float acc[2][8][4];
#pragma unroll
    for (int mf = 0; mf < 2; mf++)
#pragma unroll
        for (int nf = 0; nf < 8; nf++)
#pragma unroll
            for (int i = 0; i < 4; i++) acc[mf][nf][i] = 0.f;

    int nch = K >> 5;    // K/32 chunks

    auto stage = [&](int buf, int k0) {
#pragma unroll
        for (int i = 0; i < 4; i++) {
            int idx = i * 256 + t;
            int row = idx >> 3;
            int c4  = (idx & 7) * 4;
            unsigned off = ((unsigned)(buf * 128 + row) * 36 + c4) * 4;
            CPA(sbaseA + off, &A[(size_t)(m0 + row) * lda + k0 + c4], (m0 + row < M) ? 16 : 0);
            CPA(sbaseB + off, &W[(size_t)(n0 + row) * K   + k0 + c4], (n0 + row < N) ? 16 : 0);
        }
    };

    auto compute = [&](int buf) {
        const float* Ab = As + buf * 128 * 36;
        const float* Bb = Bs + buf * 128 * 36;
#pragma unroll
        for (int ks = 0; ks < 4; ks++) {
            int kb = ks * 8;
            unsigned a[2][4];
#pragma unroll
            for (int mf = 0; mf < 2; mf++) {
                int mr = wm + mf * 16 + r;
                a[mf][0] = __float_as_uint(Ab[(mr    ) * 36 + kb + c]);
                a[mf][1] = __float_as_uint(Ab[(mr + 8) * 36 + kb + c]);
                a[mf][2] = __float_as_uint(Ab[(mr    ) * 36 + kb + c + 4]);
                a[mf][3] = __float_as_uint(Ab[(mr + 8) * 36 + kb + c + 4]);
            }
#pragma unroll
            for (int nf = 0; nf < 8; nf++) {
                int nr = wn + nf * 8 + r;
                unsigned b[2];
                b[0] = __float_as_uint(Bb[nr * 36 + kb + c]);
                b[1] = __float_as_uint(Bb[nr * 36 + kb + c + 4]);
                mma_tf32v(acc[0][nf], a[0], b);
                mma_tf32v(acc[1][nf], a[1], b);
            }
        }
    };

    // prologue: 2 chunks in flight
    stage(0, 0);  CPC();
    stage(1, 32); CPC();

    for (int ci = 0; ci < nch; ci++) {
        if (ci < nch - 1) { CPW1(); } else { CPW0(); }
        __syncthreads();
        compute(ci & 1);
        __syncthreads();
        if (ci + 2 < nch) { stage(ci & 1, (ci + 2) * 32); CPC(); }
    }

    // epilogue
#pragma unroll
    for (int mf = 0; mf < 2; mf++) {
#pragma unroll
        for (int nf = 0; nf < 8; nf++) {
            int n = n0 + wn + nf * 8 + 2 * c;
            if (n >= N) continue;
            float bv0 = bias[n];
            float bv1 = bias[n + 1];
            int m = m0 + wm + mf * 16 + r;
            if (m < M) {
                *(float2*)&C[(size_t)m * N + n] =
                    make_float2(acc[mf][nf][0] + bv0, acc[mf][nf][1] + bv1);
            }
            if (m + 8 < M) {
                *(float2*)&C[(size_t)(m + 8) * N + n] =
                    make_float2(acc[mf][nf][2] + bv0, acc[mf][nf][3] + bv1);
            }
        }
    }
}

// ---------------- driver ----------------
extern "C" void kernel_launch(void* const* d_in, const int* in_sizes, int n_in,
                              void* d_out, int out_size) {
    const int* x         = (const int*)d_in[0];
    const float* emb     = (const float*)d_in[1];
    const float* eWih0   = (const float*)d_in[2];
    const float* eWhh0   = (const float*)d_in[3];
    const float* ebih0   = (const float*)d_in[4];
    const float* ebhh0   = (const float*)d_in[5];
    const float* eWih1   = (const float*)d_in[6];
    const float* eWhh1   = (const float*)d_in[7];
    const float* ebih1   = (const float*)d_in[8];
    const float* ebhh1   = (const float*)d_in[9];
    const float* dWih0   = (const float*)d_in[10];
    const float* dWhh0   = (const float*)d_in[11];
    const float* dbih0   = (const float*)d_in[12];
    const float* dbhh0   = (const float*)d_in[13];
    const float* dWih1   = (const float*)d_in[14];
    const float* dWhh1   = (const float*)d_in[15];
    const float* dbih1   = (const float*)d_in[16];
    const float* dbhh1   = (const float*)d_in[17];
    const float* fcW     = (const float*)d_in[18];
    const float* fcb     = (const float*)d_in[19];
    const float* recW    = (const float*)d_in[20];
    const float* recb    = (const float*)d_in[21];

    float* out = (float*)d_out;          // (64, 20)
    float* rec = out + 64 * 20;          // (64, 100, 10000)

    float *e, *gi, *y, *fcin, *fcin_tf, *wt, *recw;
    cudaGetSymbolAddress((void**)&e,       g_e);
    cudaGetSymbolAddress((void**)&gi,      g_gi);
    cudaGetSymbolAddress((void**)&y,       g_y);
    cudaGetSymbolAddress((void**)&fcin,    g_fcin);
    cudaGetSymbolAddress((void**)&fcin_tf, g_fcin_tf);
    cudaGetSymbolAddress((void**)&wt,      g_wt);
    cudaGetSymbolAddress((void**)&recw,    g_recw);

    cudaFuncSetAttribute(mma_tn, cudaFuncAttributeMaxDynamicSharedMemorySize, MMA_SMEM);

    dim3 gruGrid(BATCH, 2);

    // 0. pre-round all GEMM weights to tf32, one launch
    cvt_all<<<3364, 256>>>((const float4*)eWih0, (float4*)(wt + 0),
                           (const float4*)eWih1, (float4*)(wt + 98304),
                           (const float4*)dWih0, (float4*)(wt + 294912),
                           (const float4*)dWih1, (float4*)(wt + 688128),
                           (const float4*)recW,  (float4*)recw);

    // 1. embedding (tf32-rounded output)
    embed_kernel<<<6400, 128>>>(x, emb, e);

    // 2. encoder layer 0
    mma_tn<<<dim3(6, 50), 256, MMA_SMEM>>>(e, 128, wt + 0, ebih0, gi, 6400, 768, 128);
    gru_kernel<<<gruGrid, 384>>>(gi, TSEQ, 1, eWhh0, ebhh0, y, fcin + 0);

    // 3. encoder layer 1
    mma_tn<<<dim3(6, 50), 256, MMA_SMEM>>>(y, 256, wt + 98304, ebih1, gi, 6400, 768, 256);
    gru_kernel<<<gruGrid, 384>>>(gi, TSEQ, 1, eWhh1, ebhh1, y, fcin + 256);

    // 4. decoder layer 0 (constant input over T)
    cvt_kernel<<<64, 256>>>(fcin, fcin_tf, 65536);
    mma_tn<<<dim3(6, 1), 256, MMA_SMEM>>>(fcin_tf, 1024, wt + 294912, dbih0, gi, 64, 768, 512);
    gru_kernel<<<gruGrid, 384>>>(gi, 1, 0, dWhh0, dbhh0, y, fcin + 512);

    // 5. decoder layer 1 (output y = rec_seq)
    mma_tn<<<dim3(6, 50), 256, MMA_SMEM>>>(y, 256, wt + 688128, dbih1, gi, 6400, 768, 256);
    gru_kernel<<<gruGrid, 384>>>(gi, TSEQ, 1, dWhh1, dbhh1, y, fcin + 768);

    // 6. classifier head (fp32 GEMV, warp per output)
    fc_kernel<<<160, 256>>>(fcin, fcW, fcb, out);

    // 7. reconstruction: rec = rec_seq @ rec_W^T + rec_b
    mma_tn<<<dim3(79, 50), 256, MMA_SMEM>>>(y, 256, recw, recb, rec, 6400, 10000, 256);
}